// round 8
// baseline (speedup 1.0000x reference)
#include <cuda_runtime.h>
#include <cuda_bf16.h>

#define VEC 16

// Single fused kernel. Each block rebuilds h_t = hadamard * signs[:,None] in
// shared, computes an "is diagonal" flag via __syncthreads_or, then takes a
// grid-uniform branch:
//  - diag path (this dataset): coalesced grid-stride streaming scale with all
//    VEC=16 LDG.128s front-batched. Measured trend: chip-wide outstanding
//    loads (occ x per-thread MLP) governs DRAM%; deep per-thread MLP beats
//    occupancy on this pattern (MLP4:79.4us, MLP8:76.5us).
//  - general fallback: per-float4 gather of the 16-elem tile + 4x16 dots.
//    Never executes for these inputs.
__global__ void __launch_bounds__(256)
had_fused_kernel(const float4* __restrict__ x, float4* __restrict__ out,
                 const float* __restrict__ hadamard,
                 const float* __restrict__ signs, unsigned n_vec) {
    __shared__ float s_ht[256];
    __shared__ __align__(16) float s_diag[16];

    int t = threadIdx.x;
    int j = t >> 4;
    int i = t & 15;
    float v = hadamard[t] * signs[j];
    s_ht[t] = v;
    if (i == j) s_diag[j] = v;
    int offdiag = __syncthreads_or((i != j) && (v != 0.0f));

    unsigned stride = gridDim.x * 256u;
    unsigned g0 = blockIdx.x * 256u + (unsigned)t;

    if (!offdiag) {
        float4 d = ((const float4*)s_diag)[t & 3];
        const float4* xp = x + g0;
        float4* op = out + g0;

        if (g0 + (VEC - 1u) * stride < n_vec) {
            // Full-range fast path: all 16 loads in flight before any store.
            float4 a[VEC];
            #pragma unroll
            for (int k = 0; k < VEC; ++k)
                a[k] = __ldcs(xp + (unsigned)k * stride);
            #pragma unroll
            for (int k = 0; k < VEC; ++k)
                __stcs(op + (unsigned)k * stride,
                       make_float4(a[k].x * d.x, a[k].y * d.y,
                                   a[k].z * d.z, a[k].w * d.w));
        } else {
            // Tail blocks: guarded (not taken when grid divides exactly).
            #pragma unroll
            for (int k = 0; k < VEC; ++k) {
                unsigned g = g0 + (unsigned)k * stride;
                if (g < n_vec) {
                    float4 a = __ldcs(&x[g]);
                    __stcs(&out[g], make_float4(a.x*d.x, a.y*d.y, a.z*d.z, a.w*d.w));
                }
            }
        }
    } else {
        // General fallback (correctness only). seg = g & 3 == t & 3.
        int seg = t & 3;
        for (int k = 0; k < VEC; ++k) {
            unsigned g = g0 + (unsigned)k * stride;
            if (g >= n_vec) continue;
            const float* xt = (const float*)(x + (g & ~3u));
            float xv[16];
            #pragma unroll
            for (int ii = 0; ii < 16; ++ii) xv[ii] = xt[ii];
            float o[4];
            #pragma unroll
            for (int jj = 0; jj < 4; ++jj) {
                int row = seg * 4 + jj;
                float acc = 0.0f;
                #pragma unroll
                for (int ii = 0; ii < 16; ++ii)
                    acc = fmaf(xv[ii], s_ht[row * 16 + ii], acc);
                o[jj] = acc;
            }
            out[g] = make_float4(o[0], o[1], o[2], o[3]);
        }
    }
}

extern "C" void kernel_launch(void* const* d_in, const int* in_sizes, int n_in,
                              void* d_out, int out_size) {
    const float* x        = (const float*)d_in[0];  // [4, 4096, 4096] f32
    const float* hadamard = (const float*)d_in[1];  // [16, 16] f32
    const float* signs    = (const float*)d_in[2];  // [16] f32
    float* out = (float*)d_out;

    unsigned n_vec = (unsigned)(in_sizes[0] / 4);   // float4 count (int input)

    unsigned per_block = 256u * VEC;
    int blocks = (int)((n_vec + per_block - 1) / per_block);
    had_fused_kernel<<<blocks, 256>>>((const float4*)x, (float4*)out,
                                      hadamard, signs, n_vec);
}

// round 10
// speedup vs baseline: 1.0090x; 1.0090x over previous
#include <cuda_runtime.h>
#include <cuda_bf16.h>

#define VEC 8

// Single fused kernel. Each block rebuilds h_t = hadamard * signs[:,None] in
// shared, computes an "is diagonal" flag via __syncthreads_or, then takes a
// grid-uniform branch:
//  - diag path (this dataset): coalesced grid-stride streaming scale with all
//    VEC=8 LDG.128s front-batched. Bracketing measured: MLP4/occ63=79.4us,
//    MLP8/occ44=76.5us, MLP16/occ34=80.1us -> MLP8 optimal. This round keeps
//    MLP8 and raises occupancy via launch_bounds(256,5) (<=48 regs).
//  - general fallback: per-float4 gather of the 16-elem tile + 4x16 dots.
//    Never executes for these inputs; spills there are harmless.
__global__ void __launch_bounds__(256, 5)
had_fused_kernel(const float4* __restrict__ x, float4* __restrict__ out,
                 const float* __restrict__ hadamard,
                 const float* __restrict__ signs, unsigned n_vec) {
    __shared__ float s_ht[256];
    __shared__ __align__(16) float s_diag[16];

    int t = threadIdx.x;
    int j = t >> 4;
    int i = t & 15;
    float v = hadamard[t] * signs[j];
    s_ht[t] = v;
    if (i == j) s_diag[j] = v;
    int offdiag = __syncthreads_or((i != j) && (v != 0.0f));

    unsigned stride = gridDim.x * 256u;
    unsigned g0 = blockIdx.x * 256u + (unsigned)t;

    if (!offdiag) {
        float4 d = ((const float4*)s_diag)[t & 3];
        const float4* xp = x + g0;
        float4* op = out + g0;

        if (g0 + 7u * stride < n_vec) {
            // Full-range fast path: all 8 loads in flight before any store.
            float4 a0 = __ldcs(xp + 0u * stride);
            float4 a1 = __ldcs(xp + 1u * stride);
            float4 a2 = __ldcs(xp + 2u * stride);
            float4 a3 = __ldcs(xp + 3u * stride);
            float4 a4 = __ldcs(xp + 4u * stride);
            float4 a5 = __ldcs(xp + 5u * stride);
            float4 a6 = __ldcs(xp + 6u * stride);
            float4 a7 = __ldcs(xp + 7u * stride);
            __stcs(op + 0u * stride, make_float4(a0.x*d.x, a0.y*d.y, a0.z*d.z, a0.w*d.w));
            __stcs(op + 1u * stride, make_float4(a1.x*d.x, a1.y*d.y, a1.z*d.z, a1.w*d.w));
            __stcs(op + 2u * stride, make_float4(a2.x*d.x, a2.y*d.y, a2.z*d.z, a2.w*d.w));
            __stcs(op + 3u * stride, make_float4(a3.x*d.x, a3.y*d.y, a3.z*d.z, a3.w*d.w));
            __stcs(op + 4u * stride, make_float4(a4.x*d.x, a4.y*d.y, a4.z*d.z, a4.w*d.w));
            __stcs(op + 5u * stride, make_float4(a5.x*d.x, a5.y*d.y, a5.z*d.z, a5.w*d.w));
            __stcs(op + 6u * stride, make_float4(a6.x*d.x, a6.y*d.y, a6.z*d.z, a6.w*d.w));
            __stcs(op + 7u * stride, make_float4(a7.x*d.x, a7.y*d.y, a7.z*d.z, a7.w*d.w));
        } else {
            // Tail blocks: guarded.
            #pragma unroll
            for (int k = 0; k < VEC; ++k) {
                unsigned g = g0 + (unsigned)k * stride;
                if (g < n_vec) {
                    float4 a = __ldcs(&x[g]);
                    __stcs(&out[g], make_float4(a.x*d.x, a.y*d.y, a.z*d.z, a.w*d.w));
                }
            }
        }
    } else {
        // General fallback (correctness only). seg = g & 3 == t & 3.
        int seg = t & 3;
        for (int k = 0; k < VEC; ++k) {
            unsigned g = g0 + (unsigned)k * stride;
            if (g >= n_vec) continue;
            const float* xt = (const float*)(x + (g & ~3u));
            float xv[16];
            #pragma unroll
            for (int ii = 0; ii < 16; ++ii) xv[ii] = xt[ii];
            float o[4];
            #pragma unroll
            for (int jj = 0; jj < 4; ++jj) {
                int row = seg * 4 + jj;
                float acc = 0.0f;
                #pragma unroll
                for (int ii = 0; ii < 16; ++ii)
                    acc = fmaf(xv[ii], s_ht[row * 16 + ii], acc);
                o[jj] = acc;
            }
            out[g] = make_float4(o[0], o[1], o[2], o[3]);
        }
    }
}

extern "C" void kernel_launch(void* const* d_in, const int* in_sizes, int n_in,
                              void* d_out, int out_size) {
    const float* x        = (const float*)d_in[0];  // [4, 4096, 4096] f32
    const float* hadamard = (const float*)d_in[1];  // [16, 16] f32
    const float* signs    = (const float*)d_in[2];  // [16] f32
    float* out = (float*)d_out;

    unsigned n_vec = (unsigned)(in_sizes[0] / 4);   // float4 count (int input)

    unsigned per_block = 256u * VEC;
    int blocks = (int)((n_vec + per_block - 1) / per_block);
    had_fused_kernel<<<blocks, 256>>>((const float4*)x, (float4*)out,
                                      hadamard, signs, n_vec);
}